// round 1
// baseline (speedup 1.0000x reference)
#include <cuda_runtime.h>

// DCN cross network:
//   x: [B=16384, D=1024] f32
//   w: [L=4, D]  b: [L=4, D]
//   xi_{l+1} = x0 * dot(xi_l, w_l) + b_l + xi_l
//
// One CTA per row, 256 threads, float4 per thread. Row data lives entirely
// in registers; per-layer scalar dot via warp-shuffle + smem reduction.

constexpr int D = 1024;
constexpr int L = 4;
constexpr int THREADS = 256;  // 256 * 4 = 1024 = D

__global__ __launch_bounds__(THREADS) void cross_network_kernel(
    const float* __restrict__ x,
    const float* __restrict__ w,
    const float* __restrict__ b,
    float* __restrict__ out)
{
    const int row = blockIdx.x;
    const int tid = threadIdx.x;
    const int lane = tid & 31;
    const int warp = tid >> 5;

    const float4* xrow = reinterpret_cast<const float4*>(x) + (size_t)row * (D / 4);

    float4 x0 = xrow[tid];
    float4 xi = x0;

    // Preload this thread's slice of all layers' weights & biases (L2-broadcast, tiny)
    float4 wv[L], bv[L];
#pragma unroll
    for (int l = 0; l < L; l++) {
        wv[l] = reinterpret_cast<const float4*>(w)[l * (D / 4) + tid];
        bv[l] = reinterpret_cast<const float4*>(b)[l * (D / 4) + tid];
    }

    __shared__ float red[THREADS / 32];

#pragma unroll
    for (int l = 0; l < L; l++) {
        // Per-thread partial dot xi . w_l over 4 elements
        float p = xi.x * wv[l].x;
        p = fmaf(xi.y, wv[l].y, p);
        p = fmaf(xi.z, wv[l].z, p);
        p = fmaf(xi.w, wv[l].w, p);

        // Warp reduction
#pragma unroll
        for (int o = 16; o > 0; o >>= 1)
            p += __shfl_xor_sync(0xffffffffu, p, o);

        if (lane == 0) red[warp] = p;
        __syncthreads();

        // All threads sum the 8 warp partials (smem broadcast, conflict-free)
        float s = red[0];
#pragma unroll
        for (int i = 1; i < THREADS / 32; i++) s += red[i];

        // xi = x0 * s + b_l + xi
        xi.x = fmaf(x0.x, s, bv[l].x + xi.x);
        xi.y = fmaf(x0.y, s, bv[l].y + xi.y);
        xi.z = fmaf(x0.z, s, bv[l].z + xi.z);
        xi.w = fmaf(x0.w, s, bv[l].w + xi.w);

        if (l < L - 1) __syncthreads();  // protect red[] before next layer's write
    }

    reinterpret_cast<float4*>(out)[(size_t)row * (D / 4) + tid] = xi;
}

extern "C" void kernel_launch(void* const* d_in, const int* in_sizes, int n_in,
                              void* d_out, int out_size)
{
    const float* x = (const float*)d_in[0];
    const float* w = (const float*)d_in[1];
    const float* b = (const float*)d_in[2];
    float* out = (float*)d_out;

    const int batch = in_sizes[0] / D;  // 16384
    cross_network_kernel<<<batch, THREADS>>>(x, w, b, out);
}